// round 15
// baseline (speedup 1.0000x reference)
#include <cuda_runtime.h>
#include <float.h>
#include <stdint.h>

#define N 8192
#define D 128
#define P 4096
#define BM 128
#define NT (N / BM)               // 64 tiles per dimension
#define NBLK (NT * (NT + 1) / 2)  // 2080 productive tiles
#define M_SCREEN (NBLK * 2)       // 4160 screened entries
#define NCAND 8
#define QSCALE 21.0f
#define INV_QS2 (1.0f / (QSCALE * QSCALE))

// ---- persistent scratch (allocation-free rule): fully rewritten every launch ----
__device__ float g_self[P];
__device__ float g_blkV[M_SCREEN];
__device__ int   g_blkI[M_SCREEN];
__device__ char  g_xq[N * D];
__device__ unsigned g_done;

// dynamic smem: 2 int8 tiles of 128 rows x 128B (granule-swizzled); the same
// region is reused by the last block to stage the 4160 screened entries.
#define TILE_BYTES 16384
#define OFF_A 0
#define OFF_B TILE_BYTES
#define DSMEM_TOTAL (2 * TILE_BYTES + 1536)

__device__ __forceinline__ void ins2(float& v1, int& i1, float& v2, int& i2,
                                     float v, int i) {
    if (v > v1) { v2 = v1; i2 = i1; v1 = v; i1 = i; }
    else if (v > v2) { v2 = v; i2 = i; }
}

__device__ __forceinline__ uint32_t smem_u32(const void* p) {
    uint32_t a;
    asm("{ .reg .u64 t; cvta.to.shared.u64 t, %1; cvt.u32.u64 %0, t; }"
        : "=r"(a) : "l"(p));
    return a;
}
__device__ __forceinline__ void ldmx4(uint32_t r[4], uint32_t addr) {
    asm volatile("ldmatrix.sync.aligned.m8n8.x4.shared.b16 {%0,%1,%2,%3}, [%4];"
                 : "=r"(r[0]), "=r"(r[1]), "=r"(r[2]), "=r"(r[3]) : "r"(addr));
}
__device__ __forceinline__ void imma16832(int d[4], const uint32_t a[4],
                                          uint32_t b0, uint32_t b1) {
    asm volatile(
        "mma.sync.aligned.m16n8k32.row.col.s32.s8.s8.s32 "
        "{%0,%1,%2,%3}, {%4,%5,%6,%7}, {%8,%9}, {%0,%1,%2,%3};"
        : "+r"(d[0]), "+r"(d[1]), "+r"(d[2]), "+r"(d[3])
        : "r"(a[0]), "r"(a[1]), "r"(a[2]), "r"(a[3]), "r"(b0), "r"(b1));
}

// Kernel 0 (fused): int8 quantize + exact self dots + g_done reset.
__global__ void prep_kernel(const float* __restrict__ x) {
    const int t = threadIdx.x;
    if (blockIdx.x == 0 && t == 0) g_done = 0;
    {
        int i = blockIdx.x * 256 + t;
        float4 v = ((const float4*)x)[i];
        char4 q;
        q.x = (char)max(-127, min(127, __float2int_rn(v.x * QSCALE)));
        q.y = (char)max(-127, min(127, __float2int_rn(v.y * QSCALE)));
        q.z = (char)max(-127, min(127, __float2int_rn(v.z * QSCALE)));
        q.w = (char)max(-127, min(127, __float2int_rn(v.w * QSCALE)));
        ((char4*)g_xq)[i] = q;
    }
    if (blockIdx.x < P / 8) {
        int w = blockIdx.x * 8 + (t >> 5);
        int lane = t & 31;
        float4 a = ((const float4*)(x + (size_t)w * D))[lane];
        float4 b = ((const float4*)(x + (size_t)(w + 1) * D))[lane];
        float s = a.x * b.x;
        s = fmaf(a.y, b.y, s);
        s = fmaf(a.z, b.z, s);
        s = fmaf(a.w, b.w, s);
#pragma unroll
        for (int o = 16; o; o >>= 1) s += __shfl_xor_sync(0xffffffffu, s, o);
        if (lane == 0) g_self[w] = s;
    }
}

// Kernel 1: int8 IMMA 128x128 Gram screen over the upper triangle (2080 blocks,
// 3 blocks/SM); per-block top-2 shfl reduce; LAST block runs the finalize inline.
__global__ __launch_bounds__(256, 3) void gram_imma_kernel(
        const float* __restrict__ x, float* __restrict__ out) {
    const int bid = blockIdx.x;
    const int tid = threadIdx.x;

    // Decode bid -> (by, bx), by <= bx < NT.
    int by = (int)((2.0 * NT + 1.0
                    - sqrt((2.0 * NT + 1.0) * (2.0 * NT + 1.0) - 8.0 * (double)bid))
                   * 0.5);
    while ((by + 1) * NT - ((by + 1) * by) / 2 <= bid) ++by;
    while (by * NT - (by * (by - 1)) / 2 > bid) --by;
    const int bx = by + (bid - (by * NT - (by * (by - 1)) / 2));

    extern __shared__ char dsm_raw[];
    char* dsm = (char*)(((uintptr_t)dsm_raw + 1023) & ~(uintptr_t)1023);
    const uint32_t sbase = smem_u32(dsm);
    const int wid = tid >> 5, lane = tid & 31;
    const int wm = wid & 1, wn = wid >> 1;
    const int rowBase = by * BM, colBase = bx * BM;

    {
        const uint4* __restrict__ xq4 = (const uint4*)g_xq;
#pragma unroll
        for (int t = tid; t < 1024; t += 256) {
            int row = t >> 3, g = t & 7;
            uint32_t dst = (uint32_t)row * 128 + (uint32_t)((g ^ (row & 7)) << 4);
            *(uint4*)(dsm + OFF_A + dst) = xq4[(size_t)(rowBase + row) * 8 + g];
            *(uint4*)(dsm + OFF_B + dst) = xq4[(size_t)(colBase + row) * 8 + g];
        }
    }
    __syncthreads();

    const int lrow8 = lane & 7;
    const int lm01 = (lane >> 3) & 1;
    const int lh   = lane >> 4;
    uint32_t aoff[4], boff[2];
    int a7[4], b7[2];
#pragma unroll
    for (int mt = 0; mt < 4; ++mt) {
        int r = wm * 64 + mt * 16 + lrow8 + lm01 * 8;
        aoff[mt] = (uint32_t)r * 128; a7[mt] = r & 7;
    }
#pragma unroll
    for (int q = 0; q < 2; ++q) {
        int r = wn * 32 + q * 16 + lrow8 + lm01 * 8;
        boff[q] = (uint32_t)r * 128; b7[q] = r & 7;
    }

    int acc[4][4][4];
#pragma unroll
    for (int mt = 0; mt < 4; ++mt)
#pragma unroll
        for (int nt = 0; nt < 4; ++nt)
#pragma unroll
            for (int r = 0; r < 4; ++r) acc[mt][nt][r] = 0;

    const uint32_t Ab = sbase + OFF_A;
    const uint32_t Bb = sbase + OFF_B;
#pragma unroll
    for (int ks = 0; ks < 4; ++ks) {
        uint32_t afr[4][4], bfr[4][2];
#pragma unroll
        for (int mt = 0; mt < 4; ++mt)
            ldmx4(afr[mt], Ab + aoff[mt]
                           + (uint32_t)(((2 * ks + lh) ^ a7[mt]) << 4));
#pragma unroll
        for (int q = 0; q < 2; ++q) {
            uint32_t tmp[4];
            ldmx4(tmp, Bb + boff[q]
                       + (uint32_t)(((2 * ks + lh) ^ b7[q]) << 4));
            bfr[2 * q][0] = tmp[0]; bfr[2 * q][1] = tmp[2];
            bfr[2 * q + 1][0] = tmp[1]; bfr[2 * q + 1][1] = tmp[3];
        }
#pragma unroll
        for (int mt = 0; mt < 4; ++mt)
#pragma unroll
            for (int nt = 0; nt < 4; ++nt)
                imma16832(acc[mt][nt], afr[mt], bfr[nt][0], bfr[nt][1]);
    }

    float v1 = -FLT_MAX, v2 = -FLT_MAX; int i1 = -1, i2 = -1;
    const int grow = rowBase + wm * 64 + (lane >> 2);
    const int gcol = colBase + wn * 32 + (lane & 3) * 2;
    if (bx > by) {
#pragma unroll
        for (int mt = 0; mt < 4; ++mt)
#pragma unroll
            for (int nt = 0; nt < 4; ++nt) {
                int gi = grow + mt * 16, gj = gcol + nt * 8;
                ins2(v1, i1, v2, i2, (float)acc[mt][nt][0] * INV_QS2, gi * N + gj);
                ins2(v1, i1, v2, i2, (float)acc[mt][nt][1] * INV_QS2, gi * N + gj + 1);
                ins2(v1, i1, v2, i2, (float)acc[mt][nt][2] * INV_QS2, (gi + 8) * N + gj);
                ins2(v1, i1, v2, i2, (float)acc[mt][nt][3] * INV_QS2, (gi + 8) * N + gj + 1);
            }
    } else {
#pragma unroll
        for (int mt = 0; mt < 4; ++mt)
#pragma unroll
            for (int nt = 0; nt < 4; ++nt) {
                int gi = grow + mt * 16, gj = gcol + nt * 8;
                if (gi < gj)
                    ins2(v1, i1, v2, i2, (float)acc[mt][nt][0] * INV_QS2, gi * N + gj);
                if (gi < gj + 1)
                    ins2(v1, i1, v2, i2, (float)acc[mt][nt][1] * INV_QS2, gi * N + gj + 1);
                if (gi + 8 < gj)
                    ins2(v1, i1, v2, i2, (float)acc[mt][nt][2] * INV_QS2, (gi + 8) * N + gj);
                if (gi + 8 < gj + 1)
                    ins2(v1, i1, v2, i2, (float)acc[mt][nt][3] * INV_QS2, (gi + 8) * N + gj + 1);
            }
    }

    // ---- intra-warp top-2 reduce, warp 0 merges, write block record ----
#pragma unroll
    for (int o = 16; o; o >>= 1) {
        float ov1 = __shfl_xor_sync(0xffffffffu, v1, o);
        int   oi1 = __shfl_xor_sync(0xffffffffu, i1, o);
        float ov2 = __shfl_xor_sync(0xffffffffu, v2, o);
        int   oi2 = __shfl_xor_sync(0xffffffffu, i2, o);
        ins2(v1, i1, v2, i2, ov1, oi1);
        ins2(v1, i1, v2, i2, ov2, oi2);
    }
    __shared__ float sV[16];
    __shared__ int   sI[16];
    if (lane == 0) {
        sV[wid * 2] = v1;     sI[wid * 2] = i1;
        sV[wid * 2 + 1] = v2; sI[wid * 2 + 1] = i2;
    }
    __syncthreads();
    if (wid == 0) {
        float mv = (lane < 16) ? sV[lane] : -FLT_MAX;
        int   mi = (lane < 16) ? sI[lane] : -1;
        float w1 = -FLT_MAX, w2 = -FLT_MAX; int j1 = -1, j2 = -1;
        ins2(w1, j1, w2, j2, mv, mi);
#pragma unroll
        for (int o = 8; o; o >>= 1) {
            float ov1 = __shfl_xor_sync(0xffffffffu, w1, o);
            int   oi1 = __shfl_xor_sync(0xffffffffu, j1, o);
            float ov2 = __shfl_xor_sync(0xffffffffu, w2, o);
            int   oi2 = __shfl_xor_sync(0xffffffffu, j2, o);
            ins2(w1, j1, w2, j2, ov1, oi1);
            ins2(w1, j1, w2, j2, ov2, oi2);
        }
        if (lane == 0) {
            g_blkV[bid * 2] = w1;     g_blkI[bid * 2] = j1;
            g_blkV[bid * 2 + 1] = w2; g_blkI[bid * 2 + 1] = j2;
        }
    }
    __syncthreads();

    // ---- last-block election (fence-then-count; output order-independent) ----
    __shared__ int isLast;
    if (tid == 0) {
        __threadfence();
        unsigned ticket = atomicAdd(&g_done, 1u);
        isLast = (ticket == NBLK - 1) ? 1 : 0;
    }
    __syncthreads();
    if (!isLast) return;

    // ================= inline finalize (one block, 256 threads) =================
    float* cv = (float*)dsm;                      // 4160 floats (reuses tile smem)
    int*   ci = (int*)(dsm + M_SCREEN * 4);       // 4160 ints
    __shared__ float wv[8];
    __shared__ int   ws[8];
    __shared__ int   candI[NCAND];
    __shared__ float exactV[NCAND];
    __shared__ float fV[2];
    __shared__ int   fI[1];
    __shared__ double sD[256];

    for (int i = tid; i < M_SCREEN; i += 256) { cv[i] = g_blkV[i]; ci[i] = g_blkI[i]; }
    __syncthreads();

    for (int c = 0; c < NCAND; ++c) {
        float bv = -FLT_MAX; int bs = 0;
        for (int i = tid; i < M_SCREEN; i += 256) {
            float v = cv[i];
            if (v > bv) { bv = v; bs = i; }
        }
#pragma unroll
        for (int o = 16; o; o >>= 1) {
            float ov = __shfl_down_sync(0xffffffffu, bv, o);
            int   os = __shfl_down_sync(0xffffffffu, bs, o);
            if (ov > bv) { bv = ov; bs = os; }
        }
        if (lane == 0) { wv[wid] = bv; ws[wid] = bs; }
        __syncthreads();
        if (wid == 0) {
            float mv = (lane < 8) ? wv[lane] : -FLT_MAX;
            int   ms = (lane < 8) ? ws[lane] : 0;
#pragma unroll
            for (int o = 4; o; o >>= 1) {
                float ov = __shfl_down_sync(0xffffffffu, mv, o);
                int   os = __shfl_down_sync(0xffffffffu, ms, o);
                if (ov > mv) { mv = ov; ms = os; }
            }
            if (lane == 0) {
                candI[c] = ci[ms];
                cv[ms] = -FLT_MAX;
            }
        }
        __syncthreads();
    }

    // Exact fp32 recompute: warp w handles candidate w (8 warps, 8 candidates).
    {
        int idx = candI[wid];
        float s = -FLT_MAX;
        if (idx >= 0) {
            int gi = idx >> 13, gj = idx & (N - 1);
            float4 a = ((const float4*)(x + (size_t)gi * D))[lane];
            float4 b = ((const float4*)(x + (size_t)gj * D))[lane];
            s = a.x * b.x;
            s = fmaf(a.y, b.y, s);
            s = fmaf(a.z, b.z, s);
            s = fmaf(a.w, b.w, s);
#pragma unroll
            for (int o = 16; o; o >>= 1) s += __shfl_xor_sync(0xffffffffu, s, o);
        }
        if (lane == 0) exactV[wid] = s;
    }
    __syncthreads();

    if (tid == 0) {
        float w1 = -FLT_MAX, w2 = -FLT_MAX; int j1 = -1, j2 = -1;
#pragma unroll
        for (int c = 0; c < NCAND; ++c) ins2(w1, j1, w2, j2, exactV[c], candI[c]);
        fV[0] = w1; fV[1] = w2; fI[0] = j1;
    }
    __syncthreads();

    const float V1 = fV[0], V2 = fV[1];
    const int   I1 = fI[0];
    double sum = 0.0;
    for (int p = tid; p < P; p += 256) {
        int sf = p * N + p + 1;
        float v = (I1 == sf) ? V2 : V1;
        sum += (double)(v / g_self[p]);
    }
    sD[tid] = sum;
    __syncthreads();
    for (int s = 128; s > 0; s >>= 1) {
        if (tid < s) sD[tid] += sD[tid + s];
        __syncthreads();
    }
    if (tid == 0) out[0] = (float)(sD[0] / (double)P);
}

extern "C" void kernel_launch(void* const* d_in, const int* in_sizes, int n_in,
                              void* d_out, int out_size) {
    const float* x = (const float*)d_in[0];
    float* out = (float*)d_out;

    cudaFuncSetAttribute(gram_imma_kernel,
                         cudaFuncAttributeMaxDynamicSharedMemorySize, DSMEM_TOTAL);

    prep_kernel<<<(N * D) / 1024, 256>>>(x);
    gram_imma_kernel<<<NBLK, 256, DSMEM_TOTAL>>>(x, out);
}

// round 16
// speedup vs baseline: 1.0908x; 1.0908x over previous
#include <cuda_runtime.h>
#include <float.h>
#include <limits.h>
#include <stdint.h>

#define N 8192
#define D 128
#define P 4096
#define BMR 128                    // tile rows
#define BMC 64                     // tile cols
#define NTC (N / BMC)              // 128 col tiles
#define NTR (N / BMR)              // 64 row tiles
#define NBLK 4160                  // sum_by (128 - 2*by)
#define M_SCREEN (NBLK * 2)        // 8320 screened entries
#define NCAND 8
#define QSCALE 21.0f
#define INV_QS2 (1.0f / (QSCALE * QSCALE))

// ---- persistent scratch (allocation-free rule): fully rewritten every launch ----
__device__ float g_self[P];
__device__ float g_blkV[M_SCREEN];
__device__ int   g_blkI[M_SCREEN];
__device__ char  g_xq[N * D];

// dynamic smem: A tile 128x128B + B tile 64x128B, granule-swizzled
#define OFF_A 0
#define OFF_B 16384
#define DSMEM_TOTAL (16384 + 8192 + 1536)
#define FINAL_SMEM (M_SCREEN * 8)     // 66.5 KB staging in final kernel

__device__ __forceinline__ void ins2f(float& v1, int& i1, float& v2, int& i2,
                                      float v, int i) {
    if (v > v1) { v2 = v1; i2 = i1; v1 = v; i1 = i; }
    else if (v > v2) { v2 = v; i2 = i; }
}
__device__ __forceinline__ void ins2i(int& v1, int& i1, int& v2, int& i2,
                                      int v, int i) {
    if (v > v1) { v2 = v1; i2 = i1; v1 = v; i1 = i; }
    else if (v > v2) { v2 = v; i2 = i; }
}

__device__ __forceinline__ uint32_t smem_u32(const void* p) {
    uint32_t a;
    asm("{ .reg .u64 t; cvta.to.shared.u64 t, %1; cvt.u32.u64 %0, t; }"
        : "=r"(a) : "l"(p));
    return a;
}
__device__ __forceinline__ void ldmx4(uint32_t r[4], uint32_t addr) {
    asm volatile("ldmatrix.sync.aligned.m8n8.x4.shared.b16 {%0,%1,%2,%3}, [%4];"
                 : "=r"(r[0]), "=r"(r[1]), "=r"(r[2]), "=r"(r[3]) : "r"(addr));
}
__device__ __forceinline__ void imma16832(int d[4], const uint32_t a[4],
                                          uint32_t b0, uint32_t b1) {
    asm volatile(
        "mma.sync.aligned.m16n8k32.row.col.s32.s8.s8.s32 "
        "{%0,%1,%2,%3}, {%4,%5,%6,%7}, {%8,%9}, {%0,%1,%2,%3};"
        : "+r"(d[0]), "+r"(d[1]), "+r"(d[2]), "+r"(d[3])
        : "r"(a[0]), "r"(a[1]), "r"(a[2]), "r"(a[3]), "r"(b0), "r"(b1));
}

// Kernel 0 (fused): int8 quantize + exact self dots.
__global__ void prep_kernel(const float* __restrict__ x) {
    const int t = threadIdx.x;
    {
        int i = blockIdx.x * 256 + t;
        float4 v = ((const float4*)x)[i];
        char4 q;
        q.x = (char)max(-127, min(127, __float2int_rn(v.x * QSCALE)));
        q.y = (char)max(-127, min(127, __float2int_rn(v.y * QSCALE)));
        q.z = (char)max(-127, min(127, __float2int_rn(v.z * QSCALE)));
        q.w = (char)max(-127, min(127, __float2int_rn(v.w * QSCALE)));
        ((char4*)g_xq)[i] = q;
    }
    if (blockIdx.x < P / 8) {
        int w = blockIdx.x * 8 + (t >> 5);
        int lane = t & 31;
        float4 a = ((const float4*)(x + (size_t)w * D))[lane];
        float4 b = ((const float4*)(x + (size_t)(w + 1) * D))[lane];
        float s = a.x * b.x;
        s = fmaf(a.y, b.y, s);
        s = fmaf(a.z, b.z, s);
        s = fmaf(a.w, b.w, s);
#pragma unroll
        for (int o = 16; o; o >>= 1) s += __shfl_xor_sync(0xffffffffu, s, o);
        if (lane == 0) g_self[w] = s;
    }
}

// Kernel 1: int8 IMMA 128x64 Gram screen tile over the triangular tile set
// (4160 blocks, 4 blocks/SM target); per-block top-2 via int-domain shfl reduce.
__global__ __launch_bounds__(256, 4) void gram_imma_kernel() {
    const int bid = blockIdx.x;
    const int tid = threadIdx.x;

    // Decode bid -> (by, bxh): row-tile by (128 rows), col-tile bxh (64 cols),
    // tiles kept where bxh >= 2*by. offset(by) = 128*by - by*(by-1).
    int by = (int)((129.0 - sqrt(129.0 * 129.0 - 4.0 * (double)bid)) * 0.5);
    while (128 * (by + 1) - (by + 1) * by <= bid) ++by;
    while (128 * by - by * (by - 1) > bid) --by;
    const int bxh = 2 * by + (bid - (128 * by - by * (by - 1)));

    extern __shared__ char dsm_raw[];
    char* dsm = (char*)(((uintptr_t)dsm_raw + 1023) & ~(uintptr_t)1023);
    const uint32_t sbase = smem_u32(dsm);
    const int wid = tid >> 5, lane = tid & 31;
    const int wm = wid & 3, wn = wid >> 2;     // warp grid 4(m) x 2(n), 32x32 tiles
    const int rowBase = by * BMR, colBase = bxh * BMC;
    const bool fullTile = (colBase >= rowBase + BMR);

    // ---- load A (128 rows) + B (64 rows) int8 tiles, granule-swizzled ----
    {
        const uint4* __restrict__ xq4 = (const uint4*)g_xq;
#pragma unroll
        for (int t = tid; t < 1024; t += 256) {
            int row = t >> 3, g = t & 7;
            uint32_t dst = (uint32_t)row * 128 + (uint32_t)((g ^ (row & 7)) << 4);
            *(uint4*)(dsm + OFF_A + dst) = xq4[(size_t)(rowBase + row) * 8 + g];
        }
#pragma unroll
        for (int t = tid; t < 512; t += 256) {
            int row = t >> 3, g = t & 7;
            uint32_t dst = (uint32_t)row * 128 + (uint32_t)((g ^ (row & 7)) << 4);
            *(uint4*)(dsm + OFF_B + dst) = xq4[(size_t)(colBase + row) * 8 + g];
        }
    }
    __syncthreads();

    const int lrow8 = lane & 7;
    const int lm01 = (lane >> 3) & 1;
    const int lh   = lane >> 4;
    uint32_t aoff[2], boff[2];
    int a7[2], b7[2];
#pragma unroll
    for (int mt = 0; mt < 2; ++mt) {
        int r = wm * 32 + mt * 16 + lrow8 + lm01 * 8;
        aoff[mt] = (uint32_t)r * 128; a7[mt] = r & 7;
    }
#pragma unroll
    for (int q = 0; q < 2; ++q) {
        int r = wn * 32 + q * 16 + lrow8 + lm01 * 8;
        boff[q] = (uint32_t)r * 128; b7[q] = r & 7;
    }

    int acc[2][4][4];
#pragma unroll
    for (int mt = 0; mt < 2; ++mt)
#pragma unroll
        for (int nt = 0; nt < 4; ++nt)
#pragma unroll
            for (int r = 0; r < 4; ++r) acc[mt][nt][r] = 0;

    const uint32_t Ab = sbase + OFF_A;
    const uint32_t Bb = sbase + OFF_B;
#pragma unroll
    for (int ks = 0; ks < 4; ++ks) {
        uint32_t afr[2][4], bfr[4][2];
#pragma unroll
        for (int mt = 0; mt < 2; ++mt)
            ldmx4(afr[mt], Ab + aoff[mt]
                           + (uint32_t)(((2 * ks + lh) ^ a7[mt]) << 4));
#pragma unroll
        for (int q = 0; q < 2; ++q) {
            uint32_t tmp[4];
            ldmx4(tmp, Bb + boff[q]
                       + (uint32_t)(((2 * ks + lh) ^ b7[q]) << 4));
            bfr[2 * q][0] = tmp[0]; bfr[2 * q][1] = tmp[2];
            bfr[2 * q + 1][0] = tmp[1]; bfr[2 * q + 1][1] = tmp[3];
        }
#pragma unroll
        for (int mt = 0; mt < 2; ++mt)
#pragma unroll
            for (int nt = 0; nt < 4; ++nt)
                imma16832(acc[mt][nt], afr[mt], bfr[nt][0], bfr[nt][1]);
    }

    // ---- epilogue: int-domain top-2 (int order == float order; dots < 2^24) ----
    int v1 = INT_MIN, v2 = INT_MIN; int i1 = -1, i2 = -1;
    const int grow = rowBase + wm * 32 + (lane >> 2);
    const int gcol = colBase + wn * 32 + (lane & 3) * 2;
    if (fullTile) {
#pragma unroll
        for (int mt = 0; mt < 2; ++mt)
#pragma unroll
            for (int nt = 0; nt < 4; ++nt) {
                int gi = grow + mt * 16, gj = gcol + nt * 8;
                ins2i(v1, i1, v2, i2, acc[mt][nt][0], gi * N + gj);
                ins2i(v1, i1, v2, i2, acc[mt][nt][1], gi * N + gj + 1);
                ins2i(v1, i1, v2, i2, acc[mt][nt][2], (gi + 8) * N + gj);
                ins2i(v1, i1, v2, i2, acc[mt][nt][3], (gi + 8) * N + gj + 1);
            }
    } else {
#pragma unroll
        for (int mt = 0; mt < 2; ++mt)
#pragma unroll
            for (int nt = 0; nt < 4; ++nt) {
                int gi = grow + mt * 16, gj = gcol + nt * 8;
                if (gi < gj)
                    ins2i(v1, i1, v2, i2, acc[mt][nt][0], gi * N + gj);
                if (gi < gj + 1)
                    ins2i(v1, i1, v2, i2, acc[mt][nt][1], gi * N + gj + 1);
                if (gi + 8 < gj)
                    ins2i(v1, i1, v2, i2, acc[mt][nt][2], (gi + 8) * N + gj);
                if (gi + 8 < gj + 1)
                    ins2i(v1, i1, v2, i2, acc[mt][nt][3], (gi + 8) * N + gj + 1);
            }
    }

    // ---- intra-warp top-2 reduce (int), warp 0 merges 8 records ----
#pragma unroll
    for (int o = 16; o; o >>= 1) {
        int ov1 = __shfl_xor_sync(0xffffffffu, v1, o);
        int oi1 = __shfl_xor_sync(0xffffffffu, i1, o);
        int ov2 = __shfl_xor_sync(0xffffffffu, v2, o);
        int oi2 = __shfl_xor_sync(0xffffffffu, i2, o);
        ins2i(v1, i1, v2, i2, ov1, oi1);
        ins2i(v1, i1, v2, i2, ov2, oi2);
    }
    __shared__ int sV[16];
    __shared__ int sI[16];
    if (lane == 0) {
        sV[wid * 2] = v1;     sI[wid * 2] = i1;
        sV[wid * 2 + 1] = v2; sI[wid * 2 + 1] = i2;
    }
    __syncthreads();
    if (wid == 0) {
        int mv = (lane < 16) ? sV[lane] : INT_MIN;
        int mi = (lane < 16) ? sI[lane] : -1;
        int w1 = INT_MIN, w2 = INT_MIN, j1 = -1, j2 = -1;
        ins2i(w1, j1, w2, j2, mv, mi);
#pragma unroll
        for (int o = 8; o; o >>= 1) {
            int ov1 = __shfl_xor_sync(0xffffffffu, w1, o);
            int oi1 = __shfl_xor_sync(0xffffffffu, j1, o);
            int ov2 = __shfl_xor_sync(0xffffffffu, w2, o);
            int oi2 = __shfl_xor_sync(0xffffffffu, j2, o);
            ins2i(w1, j1, w2, j2, ov1, oi1);
            ins2i(w1, j1, w2, j2, ov2, oi2);
        }
        if (lane == 0) {
            g_blkV[bid * 2] = (j1 >= 0) ? (float)w1 * INV_QS2 : -FLT_MAX;
            g_blkI[bid * 2] = j1;
            g_blkV[bid * 2 + 1] = (j2 >= 0) ? (float)w2 * INV_QS2 : -FLT_MAX;
            g_blkI[bid * 2 + 1] = j2;
        }
    }
}

// Kernel 2 (512 threads): finalize — stage 8320 screened entries (dyn smem),
// 8x shfl-argmax, exact fp32 recompute, exact top-2, ratio mean (double acc).
__global__ __launch_bounds__(512) void final_kernel(const float* __restrict__ x,
                                                    float* __restrict__ out) {
    extern __shared__ char fsm[];
    float* cv = (float*)fsm;                    // 8320 floats
    int*   ci = (int*)(fsm + M_SCREEN * 4);     // 8320 ints
    __shared__ float wv[16];
    __shared__ int   ws[16];
    __shared__ int   candI[NCAND];
    __shared__ float exactV[NCAND];
    __shared__ float fV[2];
    __shared__ int   fI[1];
    __shared__ double sD[512];
    const int t = threadIdx.x;
    const int wid = t >> 5, lane = t & 31;

    for (int i = t; i < M_SCREEN; i += 512) { cv[i] = g_blkV[i]; ci[i] = g_blkI[i]; }
    __syncthreads();

    for (int c = 0; c < NCAND; ++c) {
        float bv = -FLT_MAX; int bs = 0;
        for (int i = t; i < M_SCREEN; i += 512) {
            float v = cv[i];
            if (v > bv) { bv = v; bs = i; }
        }
#pragma unroll
        for (int o = 16; o; o >>= 1) {
            float ov = __shfl_down_sync(0xffffffffu, bv, o);
            int   os = __shfl_down_sync(0xffffffffu, bs, o);
            if (ov > bv) { bv = ov; bs = os; }
        }
        if (lane == 0) { wv[wid] = bv; ws[wid] = bs; }
        __syncthreads();
        if (wid == 0) {
            float mv = (lane < 16) ? wv[lane] : -FLT_MAX;
            int   ms = (lane < 16) ? ws[lane] : 0;
#pragma unroll
            for (int o = 8; o; o >>= 1) {
                float ov = __shfl_down_sync(0xffffffffu, mv, o);
                int   os = __shfl_down_sync(0xffffffffu, ms, o);
                if (ov > mv) { mv = ov; ms = os; }
            }
            if (lane == 0) {
                candI[c] = ci[ms];
                cv[ms] = -FLT_MAX;
            }
        }
        __syncthreads();
    }

    if (wid < NCAND) {
        int idx = candI[wid];
        float s = -FLT_MAX;
        if (idx >= 0) {
            int gi = idx >> 13, gj = idx & (N - 1);
            float4 a = ((const float4*)(x + (size_t)gi * D))[lane];
            float4 b = ((const float4*)(x + (size_t)gj * D))[lane];
            s = a.x * b.x;
            s = fmaf(a.y, b.y, s);
            s = fmaf(a.z, b.z, s);
            s = fmaf(a.w, b.w, s);
#pragma unroll
            for (int o = 16; o; o >>= 1) s += __shfl_xor_sync(0xffffffffu, s, o);
        }
        if (lane == 0) exactV[wid] = s;
    }
    __syncthreads();

    if (t == 0) {
        float v1 = -FLT_MAX, v2 = -FLT_MAX; int i1 = -1, i2 = -1;
#pragma unroll
        for (int c = 0; c < NCAND; ++c) ins2f(v1, i1, v2, i2, exactV[c], candI[c]);
        fV[0] = v1; fV[1] = v2; fI[0] = i1;
    }
    __syncthreads();

    const float V1 = fV[0], V2 = fV[1];
    const int   I1 = fI[0];
    double sum = 0.0;
    for (int p = t; p < P; p += 512) {
        int sf = p * N + p + 1;
        float v = (I1 == sf) ? V2 : V1;
        sum += (double)(v / g_self[p]);
    }
    sD[t] = sum;
    __syncthreads();
    for (int s = 256; s > 0; s >>= 1) {
        if (t < s) sD[t] += sD[t + s];
        __syncthreads();
    }
    if (t == 0) out[0] = (float)(sD[0] / (double)P);
}

extern "C" void kernel_launch(void* const* d_in, const int* in_sizes, int n_in,
                              void* d_out, int out_size) {
    const float* x = (const float*)d_in[0];
    float* out = (float*)d_out;

    cudaFuncSetAttribute(gram_imma_kernel,
                         cudaFuncAttributeMaxDynamicSharedMemorySize, DSMEM_TOTAL);
    cudaFuncSetAttribute(final_kernel,
                         cudaFuncAttributeMaxDynamicSharedMemorySize, FINAL_SMEM);

    prep_kernel<<<(N * D) / 1024, 256>>>(x);
    gram_imma_kernel<<<NBLK, 256, DSMEM_TOTAL>>>();
    final_kernel<<<1, 512, FINAL_SMEM>>>(x, out);
}